// round 2
// baseline (speedup 1.0000x reference)
#include <cuda_runtime.h>
#include <cstdint>

#define FULL_MASK 0xFFFFFFFFu
#define NQ 8
#define DEPTH 3
#define FDIM 512
#define NCLS 10

// Deferred-CNOT linear-map masks (GF(2)):
// C (per-layer CNOT block) rows: FE 03 07 0F 1F 3F 7F FF
// pairmask[l][q] = column q of C^-l ; paritymask[l][q] = row q of C^l
// final Z masks = rows of C^3: 32 56 AC 59 B3 66 CC 99

// Apply 1-qubit gate with pair mask PM and parity mask W.
// Amp layout: index p = (lane<<3)|r ; r bits = physical bits 0..2, lane bits = 3..7.
template<int PM, int W>
__device__ __forceinline__ void gate_apply(float ar[8], float ai[8],
                                           float4 A, float4 Bv, int lane)
{
    constexpr int pr = PM & 7;
    constexpr int pl = PM >> 3;
    constexpr int wr = W & 7;
    constexpr int wl = W >> 3;
    const float2 u00 = make_float2(A.x, A.y),  u01 = make_float2(A.z, A.w);
    const float2 u10 = make_float2(Bv.x, Bv.y), u11 = make_float2(Bv.z, Bv.w);
    bool bL = (wl != 0) && ((__popc(lane & wl) & 1) != 0);
    // coeffs for amps whose r-parity is 0 (A) / 1 (B)
    float2 oA = bL ? u11 : u00, pA = bL ? u10 : u01;
    float2 oB = bL ? u00 : u11, pB = bL ? u01 : u10;

    if constexpr (pl == 0) {
        #pragma unroll
        for (int r = 0; r < 8; r++) {
            if (((0x96 >> (r & wr)) & 1) == 0) {   // base of pair (folds at compile time)
                const int r1 = r ^ pr;
                float a0r = ar[r],  a0i = ai[r];
                float a1r = ar[r1], a1i = ai[r1];
                ar[r]  = oA.x * a0r - oA.y * a0i + pA.x * a1r - pA.y * a1i;
                ai[r]  = oA.x * a0i + oA.y * a0r + pA.x * a1i + pA.y * a1r;
                ar[r1] = oB.x * a1r - oB.y * a1i + pB.x * a0r - pB.y * a0i;
                ai[r1] = oB.x * a1i + oB.y * a1r + pB.x * a0i + pB.y * a0r;
            }
        }
    } else {
        float tr[8], ti[8];
        #pragma unroll
        for (int r = 0; r < 8; r++) {
            tr[r] = __shfl_xor_sync(FULL_MASK, ar[r ^ pr], pl);
            ti[r] = __shfl_xor_sync(FULL_MASK, ai[r ^ pr], pl);
        }
        #pragma unroll
        for (int r = 0; r < 8; r++) {
            const bool pb = ((0x96 >> (r & wr)) & 1) != 0;   // compile-time
            float2 o = pb ? oB : oA;
            float2 p = pb ? pB : pA;
            float nr = o.x * ar[r] - o.y * ai[r] + p.x * tr[r] - p.y * ti[r];
            float ni = o.x * ai[r] + o.y * ar[r] + p.x * ti[r] + p.y * tr[r];
            ar[r] = nr; ai[r] = ni;
        }
    }
}

__global__ void __launch_bounds__(256, 4) qiskit_head_kernel(
    const float* __restrict__ x,       // (B, 512)
    const float* __restrict__ proj_w,  // (8, 512)
    const float* __restrict__ qnn_w,   // (72,)
    const float* __restrict__ out_w,   // (10, 8)
    const float* __restrict__ out_b,   // (10,)
    float* __restrict__ out,           // (B, 10)
    int B)
{
    __shared__ __align__(16) float s_pw[NQ * FDIM];   // 16 KB
    __shared__ float4 s_g4[DEPTH * NQ][2];            // fused RX*RY*RX gates
    __shared__ float  s_ow[NCLS * NQ];
    __shared__ float  s_ob[NCLS];

    const int tid  = threadIdx.x;
    const int lane = tid & 31;
    const int warp = tid >> 5;

    // ---- block-shared setup ----
    #pragma unroll 4
    for (int i = tid; i < NQ * FDIM; i += 256) s_pw[i] = proj_w[i];
    if (tid < NCLS * NQ) s_ow[tid] = out_w[tid];
    if (tid < NCLS)      s_ob[tid] = out_b[tid];
    if (tid < DEPTH * NQ) {
        float w0 = qnn_w[tid * 3 + 0];
        float w1 = qnn_w[tid * 3 + 1];
        float w2 = qnn_w[tid * 3 + 2];
        float c0, s0, c1, s1, c2, s2;
        sincosf(0.5f * w0, &s0, &c0);
        sincosf(0.5f * w1, &s1, &c1);
        sincosf(0.5f * w2, &s2, &c2);
        // A = RY(w1)*RX(w0);  M = RX(w2)*A
        float2 A00 = { c1 * c0,  s1 * s0};
        float2 A01 = {-s1 * c0, -c1 * s0};
        float2 A10 = { s1 * c0, -c1 * s0};
        float2 A11 = { c1 * c0, -s1 * s0};
        float2 g00 = make_float2(c2 * A00.x + s2 * A10.y, c2 * A00.y - s2 * A10.x);
        float2 g01 = make_float2(c2 * A01.x + s2 * A11.y, c2 * A01.y - s2 * A11.x);
        float2 g10 = make_float2(c2 * A10.x + s2 * A00.y, c2 * A10.y - s2 * A00.x);
        float2 g11 = make_float2(c2 * A11.x + s2 * A01.y, c2 * A11.y - s2 * A01.x);
        s_g4[tid][0] = make_float4(g00.x, g00.y, g01.x, g01.y);
        s_g4[tid][1] = make_float4(g10.x, g10.y, g11.x, g11.y);
    }
    __syncthreads();

    // multi-value merge reduce helper
    auto mrg = [&](float a, float b, int dist) {
        float c = (lane & dist) ? b : a;
        float d = (lane & dist) ? a : b;
        return c + __shfl_xor_sync(FULL_MASK, d, dist);
    };
    // lane group -> q mapping: q = b4 | (b3<<1) | (b2<<2); source lane of q:
    auto srcLane = [](int q) { return ((q & 1) << 4) | (((q >> 1) & 1) << 3) | (((q >> 2) & 1) << 2); };

    const int wstride = gridDim.x * 8;
    for (int b = blockIdx.x * 8 + warp; b < B; b += wstride) {

        // ---- projection: acc[q] = x[b] . proj_w[q] ----
        float acc[NQ];
        #pragma unroll
        for (int q = 0; q < NQ; q++) acc[q] = 0.f;
        const float4* xr = (const float4*)(x + (size_t)b * FDIM);
        #pragma unroll
        for (int ch = 0; ch < 4; ch++) {
            float4 xv = xr[ch * 32 + lane];
            #pragma unroll
            for (int q = 0; q < NQ; q++) {
                float4 wv = *(const float4*)&s_pw[q * FDIM + ch * 128 + lane * 4];
                acc[q] += xv.x * wv.x + xv.y * wv.y + xv.z * wv.z + xv.w * wv.w;
            }
        }
        // 9-shfl multi-reduce: lane group (bits 4,3,2) ends with total for its q
        {
            float m0 = mrg(acc[0], acc[1], 16), m1 = mrg(acc[2], acc[3], 16);
            float m2 = mrg(acc[4], acc[5], 16), m3 = mrg(acc[6], acc[7], 16);
            float n0 = mrg(m0, m1, 8), n1 = mrg(m2, m3, 8);
            float f  = mrg(n0, n1, 4);
            f += __shfl_xor_sync(FULL_MASK, f, 2);
            f += __shfl_xor_sync(FULL_MASK, f, 1);
            acc[0] = f;
        }
        // one tanh+sincos per lane, then broadcast
        float cv, sv;
        {
            float h = tanhf(acc[0]) * 0.78539816339744830962f;  // half-angle
            __sincosf(h, &sv, &cv);
        }
        float cq[NQ], sq[NQ];
        #pragma unroll
        for (int q = 0; q < NQ; q++) {
            cq[q] = __shfl_sync(FULL_MASK, cv, srcLane(q));
            sq[q] = __shfl_sync(FULL_MASK, sv, srcLane(q));
        }

        // ---- initial product state (RY encoding of |0..0>) ----
        float lp = 1.f;
        #pragma unroll
        for (int k = 0; k < 5; k++) lp *= ((lane >> k) & 1) ? sq[k + 3] : cq[k + 3];
        float ar[8], ai[8];
        #pragma unroll
        for (int r = 0; r < 8; r++) {
            float rp = ((r & 1) ? sq[0] : cq[0]) *
                       ((r & 2) ? sq[1] : cq[1]) *
                       ((r & 4) ? sq[2] : cq[2]);
            ar[r] = lp * rp;
            ai[r] = 0.f;
        }

        // ---- circuit: gates with deferred-CNOT masks ----
        #define GATE(idx, PMv, Wv) gate_apply<PMv, Wv>(ar, ai, s_g4[idx][0], s_g4[idx][1], lane)
        // layer 0 (phi = I)
        GATE(0, 0x01, 0x01); GATE(1, 0x02, 0x02); GATE(2, 0x04, 0x04); GATE(3, 0x08, 0x08);
        GATE(4, 0x10, 0x10); GATE(5, 0x20, 0x20); GATE(6, 0x40, 0x40); GATE(7, 0x80, 0x80);
        // layer 1 (phi = C)
        GATE(8,  0x03, 0xFE); GATE(9,  0x06, 0x03); GATE(10, 0x0C, 0x07); GATE(11, 0x18, 0x0F);
        GATE(12, 0x30, 0x1F); GATE(13, 0x60, 0x3F); GATE(14, 0xC0, 0x7F); GATE(15, 0x83, 0xFF);
        // layer 2 (phi = C^2)
        GATE(16, 0x05, 0xAB); GATE(17, 0x0A, 0xFD); GATE(18, 0x14, 0xFA); GATE(19, 0x28, 0xF5);
        GATE(20, 0x50, 0xEA); GATE(21, 0xA0, 0xD5); GATE(22, 0x43, 0xAA); GATE(23, 0x86, 0x55);
        #undef GATE

        // ---- PauliZ via Walsh-Hadamard of |amp|^2 (phi = C^3) ----
        float S[8];
        #pragma unroll
        for (int r = 0; r < 8; r++) S[r] = ar[r] * ar[r] + ai[r] * ai[r];
        #pragma unroll
        for (int st = 0; st < 3; st++) {
            const int d = 1 << st;
            #pragma unroll
            for (int r = 0; r < 8; r++) {
                if (!(r & d)) {
                    float a = S[r] + S[r + d];
                    float bm = S[r] - S[r + d];
                    S[r] = a; S[r + d] = bm;
                }
            }
        }
        // final masks: (wr, wl) per q from rows of C^3
        auto sg = [&](int wl, float v) { return (__popc(lane & wl) & 1) ? -v : v; };
        float z0 = sg(0x06, S[2]), z1 = sg(0x0A, S[6]);
        float z2 = sg(0x15, S[4]), z3 = sg(0x0B, S[1]);
        float z4 = sg(0x16, S[3]), z5 = sg(0x0C, S[6]);
        float z6 = sg(0x19, S[4]), z7 = sg(0x13, S[1]);
        // 9-shfl multi-reduce over lanes
        float m0 = mrg(z0, z1, 16), m1 = mrg(z2, z3, 16);
        float m2 = mrg(z4, z5, 16), m3 = mrg(z6, z7, 16);
        float n0 = mrg(m0, m1, 8),  n1 = mrg(m2, m3, 8);
        float f  = mrg(n0, n1, 4);
        f += __shfl_xor_sync(FULL_MASK, f, 2);
        f += __shfl_xor_sync(FULL_MASK, f, 1);
        // gather all 8 expectations to every lane
        float g[NQ];
        #pragma unroll
        for (int q = 0; q < NQ; q++) g[q] = __shfl_sync(FULL_MASK, f, srcLane(q));

        // ---- output head ----
        if (lane < NCLS) {
            float o = s_ob[lane];
            #pragma unroll
            for (int q = 0; q < NQ; q++) o += g[q] * s_ow[lane * NQ + q];
            out[(size_t)b * NCLS + lane] = o;
        }
    }
}

extern "C" void kernel_launch(void* const* d_in, const int* in_sizes, int n_in,
                              void* d_out, int out_size) {
    const float* x      = (const float*)d_in[0];
    const float* proj_w = (const float*)d_in[1];
    const float* qnn_w  = (const float*)d_in[2];
    const float* out_w  = (const float*)d_in[3];
    const float* out_b  = (const float*)d_in[4];
    float* out = (float*)d_out;

    int B = in_sizes[0] / FDIM;   // 8192
    int blocks = 512;             // grid-stride: 2 batch elems per warp
    qiskit_head_kernel<<<blocks, 256>>>(x, proj_w, qnn_w, out_w, out_b, out, B);
}

// round 3
// speedup vs baseline: 1.4486x; 1.4486x over previous
#include <cuda_runtime.h>
#include <cstdint>

#define FULL_MASK 0xFFFFFFFFu
#define NQ 8
#define DEPTH 3
#define FDIM 512
#define NCLS 10

// Deferred-CNOT linear-map masks (GF(2)):
// C (per-layer CNOT block) rows: FE 03 07 0F 1F 3F 7F FF
// pairmask[l][q] = column q of C^-l ; paritymask[l][q] = row q of C^l
// final Z masks = rows of C^3.
// Amp layout: p = (lane<<3)|r ; r bits = qubit bits 0..2, lane bits = 3..7.

// parity table for 3-bit values: 0x96
template<int PM, int W>
__device__ __forceinline__ void gate_apply(float ar[8], float ai[8],
                                           float4 A, float4 Bv, int lane)
{
    constexpr int pr = PM & 7;
    constexpr int pl = PM >> 3;
    constexpr int wr = W & 7;
    constexpr int wl = W >> 3;
    const float2 u00 = make_float2(A.x, A.y),  u01 = make_float2(A.z, A.w);
    const float2 u10 = make_float2(Bv.x, Bv.y), u11 = make_float2(Bv.z, Bv.w);
    bool bL = (wl != 0) && ((__popc(lane & wl) & 1) != 0);
    float2 oA = bL ? u11 : u00, pA = bL ? u10 : u01;
    float2 oB = bL ? u00 : u11, pB = bL ? u01 : u10;

    if constexpr (pl == 0) {
        // register-resident pairing
        #pragma unroll
        for (int r = 0; r < 8; r++) {
            if (((0x96 >> (r & wr)) & 1) == 0) {   // base of pair (compile-time)
                const int r1 = r ^ pr;
                float a0r = ar[r],  a0i = ai[r];
                float a1r = ar[r1], a1i = ai[r1];
                ar[r]  = oA.x * a0r - oA.y * a0i + pA.x * a1r - pA.y * a1i;
                ai[r]  = oA.x * a0i + oA.y * a0r + pA.x * a1i + pA.y * a1r;
                ar[r1] = oB.x * a1r - oB.y * a1i + pB.x * a0r - pB.y * a0i;
                ai[r1] = oB.x * a1i + oB.y * a1r + pB.x * a0i + pB.y * a0r;
            }
        }
    } else if constexpr (pr == 0) {
        // partner = same r slot in lane^pl: stream one r at a time (2 temps)
        #pragma unroll
        for (int r = 0; r < 8; r++) {
            float tr = __shfl_xor_sync(FULL_MASK, ar[r], pl);
            float ti = __shfl_xor_sync(FULL_MASK, ai[r], pl);
            const bool pb = ((0x96 >> (r & wr)) & 1) != 0;   // compile-time
            float2 o = pb ? oB : oA;
            float2 p = pb ? pB : pA;
            float nr = o.x * ar[r] - o.y * ai[r] + p.x * tr - p.y * ti;
            float ni = o.x * ai[r] + o.y * ar[r] + p.x * ti + p.y * tr;
            ar[r] = nr; ai[r] = ni;
        }
    } else {
        // partner = r^pr in lane^pl: process pairs (4 temps)
        #pragma unroll
        for (int r = 0; r < 8; r++) {
            if (r < (r ^ pr)) {                       // compile-time pair rep
                const int r1 = r ^ pr;
                float sr0 = __shfl_xor_sync(FULL_MASK, ar[r1], pl);
                float si0 = __shfl_xor_sync(FULL_MASK, ai[r1], pl);
                float sr1 = __shfl_xor_sync(FULL_MASK, ar[r],  pl);
                float si1 = __shfl_xor_sync(FULL_MASK, ai[r],  pl);
                const bool pb0 = ((0x96 >> (r  & wr)) & 1) != 0;
                const bool pb1 = ((0x96 >> (r1 & wr)) & 1) != 0;
                float2 o0 = pb0 ? oB : oA, p0 = pb0 ? pB : pA;
                float2 o1 = pb1 ? oB : oA, p1 = pb1 ? pB : pA;
                float nr0 = o0.x * ar[r]  - o0.y * ai[r]  + p0.x * sr0 - p0.y * si0;
                float ni0 = o0.x * ai[r]  + o0.y * ar[r]  + p0.x * si0 + p0.y * sr0;
                float nr1 = o1.x * ar[r1] - o1.y * ai[r1] + p1.x * sr1 - p1.y * si1;
                float ni1 = o1.x * ai[r1] + o1.y * ar[r1] + p1.x * si1 + p1.y * sr1;
                ar[r]  = nr0; ai[r]  = ni0;
                ar[r1] = nr1; ai[r1] = ni1;
            }
        }
    }
}

__global__ void __launch_bounds__(256, 5) qiskit_head_kernel(
    const float* __restrict__ x,       // (B, 512)
    const float* __restrict__ proj_w,  // (8, 512)
    const float* __restrict__ qnn_w,   // (72,)
    const float* __restrict__ out_w,   // (10, 8)
    const float* __restrict__ out_b,   // (10,)
    float* __restrict__ out,           // (B, 10)
    int B)
{
    __shared__ __align__(16) float s_pw[NQ * FDIM];   // 16 KB
    __shared__ float4 s_g4[DEPTH * NQ][2];            // fused RX*RY*RX gates
    __shared__ float  s_ow[NCLS * NQ];
    __shared__ float  s_ob[NCLS];

    const int tid  = threadIdx.x;
    const int lane = tid & 31;
    const int warp = tid >> 5;

    // ---- block-shared setup ----
    #pragma unroll 4
    for (int i = tid; i < NQ * FDIM; i += 256) s_pw[i] = proj_w[i];
    if (tid < NCLS * NQ) s_ow[tid] = out_w[tid];
    if (tid < NCLS)      s_ob[tid] = out_b[tid];
    if (tid < DEPTH * NQ) {
        float w0 = qnn_w[tid * 3 + 0];
        float w1 = qnn_w[tid * 3 + 1];
        float w2 = qnn_w[tid * 3 + 2];
        float c0, s0, c1, s1, c2, s2;
        sincosf(0.5f * w0, &s0, &c0);
        sincosf(0.5f * w1, &s1, &c1);
        sincosf(0.5f * w2, &s2, &c2);
        // A = RY(w1)*RX(w0);  M = RX(w2)*A
        float2 A00 = { c1 * c0,  s1 * s0};
        float2 A01 = {-s1 * c0, -c1 * s0};
        float2 A10 = { s1 * c0, -c1 * s0};
        float2 A11 = { c1 * c0, -s1 * s0};
        float2 g00 = make_float2(c2 * A00.x + s2 * A10.y, c2 * A00.y - s2 * A10.x);
        float2 g01 = make_float2(c2 * A01.x + s2 * A11.y, c2 * A01.y - s2 * A11.x);
        float2 g10 = make_float2(c2 * A10.x + s2 * A00.y, c2 * A10.y - s2 * A00.x);
        float2 g11 = make_float2(c2 * A11.x + s2 * A01.y, c2 * A11.y - s2 * A01.x);
        s_g4[tid][0] = make_float4(g00.x, g00.y, g01.x, g01.y);
        s_g4[tid][1] = make_float4(g10.x, g10.y, g11.x, g11.y);
    }
    __syncthreads();

    auto mrg = [&](float a, float b, int dist) {
        float c = (lane & dist) ? b : a;
        float d = (lane & dist) ? a : b;
        return c + __shfl_xor_sync(FULL_MASK, d, dist);
    };
    auto srcLane = [](int q) { return ((q & 1) << 4) | (((q >> 1) & 1) << 3) | (((q >> 2) & 1) << 2); };

    const int b = blockIdx.x * 8 + warp;
    if (b >= B) return;   // warp-uniform

    // ---- projection: acc[q] = x[b] . proj_w[q] ----
    float acc[NQ];
    #pragma unroll
    for (int q = 0; q < NQ; q++) acc[q] = 0.f;
    const float4* xr = (const float4*)(x + (size_t)b * FDIM);
    #pragma unroll
    for (int ch = 0; ch < 4; ch++) {
        float4 xv = xr[ch * 32 + lane];
        #pragma unroll
        for (int q = 0; q < NQ; q++) {
            float4 wv = *(const float4*)&s_pw[q * FDIM + ch * 128 + lane * 4];
            acc[q] += xv.x * wv.x + xv.y * wv.y + xv.z * wv.z + xv.w * wv.w;
        }
    }
    // 9-shfl multi-reduce: lane group (bits 4,3,2) holds total for its q
    {
        float m0 = mrg(acc[0], acc[1], 16), m1 = mrg(acc[2], acc[3], 16);
        float m2 = mrg(acc[4], acc[5], 16), m3 = mrg(acc[6], acc[7], 16);
        float n0 = mrg(m0, m1, 8), n1 = mrg(m2, m3, 8);
        float f  = mrg(n0, n1, 4);
        f += __shfl_xor_sync(FULL_MASK, f, 2);
        f += __shfl_xor_sync(FULL_MASK, f, 1);
        acc[0] = f;
    }
    // one tanh+sincos per lane, then broadcast half-angle cos/sin
    float cv, sv;
    {
        float h = tanhf(acc[0]) * 0.78539816339744830962f;
        __sincosf(h, &sv, &cv);
    }
    float cq[NQ], sq[NQ];
    #pragma unroll
    for (int q = 0; q < NQ; q++) {
        cq[q] = __shfl_sync(FULL_MASK, cv, srcLane(q));
        sq[q] = __shfl_sync(FULL_MASK, sv, srcLane(q));
    }

    // ---- state after encoding + layer-0 gates: product state ----
    // v_q = M_{0,q} . (c,s)^T ; amp(p) = prod_q v_q[bit_q(p)]
    float Lr = 1.f, Li = 0.f;
    #pragma unroll
    for (int k = 0; k < 5; k++) {
        const int q = k + 3;
        float4 A = s_g4[q][0], Bv = s_g4[q][1];
        const bool bit = (lane >> k) & 1;
        float wx = bit ? (Bv.x * cq[q] + Bv.z * sq[q]) : (A.x * cq[q] + A.z * sq[q]);
        float wy = bit ? (Bv.y * cq[q] + Bv.w * sq[q]) : (A.y * cq[q] + A.w * sq[q]);
        float nr = Lr * wx - Li * wy;
        float ni = Lr * wy + Li * wx;
        Lr = nr; Li = ni;
    }
    float ar[8], ai[8];
    {
        float4 A0 = s_g4[0][0], B0 = s_g4[0][1];
        float a0x = A0.x * cq[0] + A0.z * sq[0], a0y = A0.y * cq[0] + A0.w * sq[0];
        float b0x = B0.x * cq[0] + B0.z * sq[0], b0y = B0.y * cq[0] + B0.w * sq[0];
        ar[0] = Lr * a0x - Li * a0y;  ai[0] = Lr * a0y + Li * a0x;
        ar[1] = Lr * b0x - Li * b0y;  ai[1] = Lr * b0y + Li * b0x;

        float4 A1 = s_g4[1][0], B1 = s_g4[1][1];
        float a1x = A1.x * cq[1] + A1.z * sq[1], a1y = A1.y * cq[1] + A1.w * sq[1];
        float b1x = B1.x * cq[1] + B1.z * sq[1], b1y = B1.y * cq[1] + B1.w * sq[1];
        #pragma unroll
        for (int r = 0; r < 2; r++) {
            float tr = ar[r], ti = ai[r];
            ar[r + 2] = tr * b1x - ti * b1y;  ai[r + 2] = tr * b1y + ti * b1x;
            ar[r]     = tr * a1x - ti * a1y;  ai[r]     = tr * a1y + ti * a1x;
        }

        float4 A2 = s_g4[2][0], B2 = s_g4[2][1];
        float a2x = A2.x * cq[2] + A2.z * sq[2], a2y = A2.y * cq[2] + A2.w * sq[2];
        float b2x = B2.x * cq[2] + B2.z * sq[2], b2y = B2.y * cq[2] + B2.w * sq[2];
        #pragma unroll
        for (int r = 0; r < 4; r++) {
            float tr = ar[r], ti = ai[r];
            ar[r + 4] = tr * b2x - ti * b2y;  ai[r + 4] = tr * b2y + ti * b2x;
            ar[r]     = tr * a2x - ti * a2y;  ai[r]     = tr * a2y + ti * a2x;
        }
    }

    // ---- layers 1,2 with deferred-CNOT masks ----
    #define GATE(idx, PMv, Wv) gate_apply<PMv, Wv>(ar, ai, s_g4[idx][0], s_g4[idx][1], lane)
    // layer 1 (phi = C)
    GATE(8,  0x03, 0xFE); GATE(9,  0x06, 0x03); GATE(10, 0x0C, 0x07); GATE(11, 0x18, 0x0F);
    GATE(12, 0x30, 0x1F); GATE(13, 0x60, 0x3F); GATE(14, 0xC0, 0x7F); GATE(15, 0x83, 0xFF);
    // layer 2 (phi = C^2)
    GATE(16, 0x05, 0xAB); GATE(17, 0x0A, 0xFD); GATE(18, 0x14, 0xFA); GATE(19, 0x28, 0xF5);
    GATE(20, 0x50, 0xEA); GATE(21, 0xA0, 0xD5); GATE(22, 0x43, 0xAA); GATE(23, 0x86, 0x55);
    #undef GATE

    // ---- PauliZ via Walsh-Hadamard of |amp|^2 (phi = C^3) ----
    float S[8];
    #pragma unroll
    for (int r = 0; r < 8; r++) S[r] = ar[r] * ar[r] + ai[r] * ai[r];
    #pragma unroll
    for (int st = 0; st < 3; st++) {
        const int d = 1 << st;
        #pragma unroll
        for (int r = 0; r < 8; r++) {
            if (!(r & d)) {
                float a = S[r] + S[r + d];
                float bm = S[r] - S[r + d];
                S[r] = a; S[r + d] = bm;
            }
        }
    }
    auto sg = [&](int wl, float v) { return (__popc(lane & wl) & 1) ? -v : v; };
    float z0 = sg(0x06, S[2]), z1 = sg(0x0A, S[6]);
    float z2 = sg(0x15, S[4]), z3 = sg(0x0B, S[1]);
    float z4 = sg(0x16, S[3]), z5 = sg(0x0C, S[6]);
    float z6 = sg(0x19, S[4]), z7 = sg(0x13, S[1]);
    float m0 = mrg(z0, z1, 16), m1 = mrg(z2, z3, 16);
    float m2 = mrg(z4, z5, 16), m3 = mrg(z6, z7, 16);
    float n0 = mrg(m0, m1, 8),  n1 = mrg(m2, m3, 8);
    float f  = mrg(n0, n1, 4);
    f += __shfl_xor_sync(FULL_MASK, f, 2);
    f += __shfl_xor_sync(FULL_MASK, f, 1);
    float g[NQ];
    #pragma unroll
    for (int q = 0; q < NQ; q++) g[q] = __shfl_sync(FULL_MASK, f, srcLane(q));

    // ---- output head ----
    if (lane < NCLS) {
        float o = s_ob[lane];
        #pragma unroll
        for (int q = 0; q < NQ; q++) o += g[q] * s_ow[lane * NQ + q];
        out[(size_t)b * NCLS + lane] = o;
    }
}

extern "C" void kernel_launch(void* const* d_in, const int* in_sizes, int n_in,
                              void* d_out, int out_size) {
    const float* x      = (const float*)d_in[0];
    const float* proj_w = (const float*)d_in[1];
    const float* qnn_w  = (const float*)d_in[2];
    const float* out_w  = (const float*)d_in[3];
    const float* out_b  = (const float*)d_in[4];
    float* out = (float*)d_out;

    int B = in_sizes[0] / FDIM;           // 8192
    int blocks = (B + 7) / 8;             // 1024: one batch element per warp
    qiskit_head_kernel<<<blocks, 256>>>(x, proj_w, qnn_w, out_w, out_b, out, B);
}

// round 4
// speedup vs baseline: 1.4503x; 1.0012x over previous
#include <cuda_runtime.h>
#include <cstdint>

#define FULL_MASK 0xFFFFFFFFu
#define NQ 8
#define DEPTH 3
#define FDIM 512
#define NCLS 10

// Deferred-CNOT masks (GF(2)); layout p = (lane<<3)|r, r = qubit bits 0..2.
// parity table for 3-bit values: 0x96
template<int PM, int W>
__device__ __forceinline__ void gate_apply2(float ar[2][8], float ai[2][8],
                                            float4 A, float4 Bv, int lane)
{
    constexpr int pr = PM & 7;
    constexpr int pl = PM >> 3;
    constexpr int wr = W & 7;
    constexpr int wl = W >> 3;
    const float2 u00 = make_float2(A.x, A.y),  u01 = make_float2(A.z, A.w);
    const float2 u10 = make_float2(Bv.x, Bv.y), u11 = make_float2(Bv.z, Bv.w);
    bool bL = (wl != 0) && ((__popc(lane & wl) & 1) != 0);
    float2 oA = bL ? u11 : u00, pA = bL ? u10 : u01;
    float2 oB = bL ? u00 : u11, pB = bL ? u01 : u10;

    if constexpr (pl == 0) {
        #pragma unroll
        for (int e = 0; e < 2; e++) {
            #pragma unroll
            for (int r = 0; r < 8; r++) {
                if (((0x96 >> (r & wr)) & 1) == 0) {   // base of pair (compile-time)
                    const int r1 = r ^ pr;
                    float a0r = ar[e][r],  a0i = ai[e][r];
                    float a1r = ar[e][r1], a1i = ai[e][r1];
                    ar[e][r]  = oA.x*a0r - oA.y*a0i + pA.x*a1r - pA.y*a1i;
                    ai[e][r]  = oA.x*a0i + oA.y*a0r + pA.x*a1i + pA.y*a1r;
                    ar[e][r1] = oB.x*a1r - oB.y*a1i + pB.x*a0r - pB.y*a0i;
                    ai[e][r1] = oB.x*a1i + oB.y*a1r + pB.x*a0i + pB.y*a0r;
                }
            }
        }
    } else if constexpr (pr == 0) {
        #pragma unroll
        for (int r = 0; r < 8; r++) {
            float tr0 = __shfl_xor_sync(FULL_MASK, ar[0][r], pl);
            float ti0 = __shfl_xor_sync(FULL_MASK, ai[0][r], pl);
            float tr1 = __shfl_xor_sync(FULL_MASK, ar[1][r], pl);
            float ti1 = __shfl_xor_sync(FULL_MASK, ai[1][r], pl);
            const bool pb = ((0x96 >> (r & wr)) & 1) != 0;
            float2 o = pb ? oB : oA;
            float2 p = pb ? pB : pA;
            float nr0 = o.x*ar[0][r] - o.y*ai[0][r] + p.x*tr0 - p.y*ti0;
            float ni0 = o.x*ai[0][r] + o.y*ar[0][r] + p.x*ti0 + p.y*tr0;
            float nr1 = o.x*ar[1][r] - o.y*ai[1][r] + p.x*tr1 - p.y*ti1;
            float ni1 = o.x*ai[1][r] + o.y*ar[1][r] + p.x*ti1 + p.y*tr1;
            ar[0][r] = nr0; ai[0][r] = ni0;
            ar[1][r] = nr1; ai[1][r] = ni1;
        }
    } else {
        #pragma unroll
        for (int r = 0; r < 8; r++) {
            if (r < (r ^ pr)) {                       // compile-time pair rep
                const int r1 = r ^ pr;
                float s0r0 = __shfl_xor_sync(FULL_MASK, ar[0][r1], pl);
                float s0i0 = __shfl_xor_sync(FULL_MASK, ai[0][r1], pl);
                float s0r1 = __shfl_xor_sync(FULL_MASK, ar[0][r],  pl);
                float s0i1 = __shfl_xor_sync(FULL_MASK, ai[0][r],  pl);
                float s1r0 = __shfl_xor_sync(FULL_MASK, ar[1][r1], pl);
                float s1i0 = __shfl_xor_sync(FULL_MASK, ai[1][r1], pl);
                float s1r1 = __shfl_xor_sync(FULL_MASK, ar[1][r],  pl);
                float s1i1 = __shfl_xor_sync(FULL_MASK, ai[1][r],  pl);
                const bool pb0 = ((0x96 >> (r  & wr)) & 1) != 0;
                const bool pb1 = ((0x96 >> (r1 & wr)) & 1) != 0;
                float2 o0 = pb0 ? oB : oA, p0 = pb0 ? pB : pA;
                float2 o1 = pb1 ? oB : oA, p1 = pb1 ? pB : pA;
                float n0r0 = o0.x*ar[0][r]  - o0.y*ai[0][r]  + p0.x*s0r0 - p0.y*s0i0;
                float n0i0 = o0.x*ai[0][r]  + o0.y*ar[0][r]  + p0.x*s0i0 + p0.y*s0r0;
                float n0r1 = o1.x*ar[0][r1] - o1.y*ai[0][r1] + p1.x*s0r1 - p1.y*s0i1;
                float n0i1 = o1.x*ai[0][r1] + o1.y*ar[0][r1] + p1.x*s0i1 + p1.y*s0r1;
                float n1r0 = o0.x*ar[1][r]  - o0.y*ai[1][r]  + p0.x*s1r0 - p0.y*s1i0;
                float n1i0 = o0.x*ai[1][r]  + o0.y*ar[1][r]  + p0.x*s1i0 + p0.y*s1r0;
                float n1r1 = o1.x*ar[1][r1] - o1.y*ai[1][r1] + p1.x*s1r1 - p1.y*s1i1;
                float n1i1 = o1.x*ai[1][r1] + o1.y*ar[1][r1] + p1.x*s1i1 + p1.y*s1r1;
                ar[0][r]  = n0r0; ai[0][r]  = n0i0;
                ar[0][r1] = n0r1; ai[0][r1] = n0i1;
                ar[1][r]  = n1r0; ai[1][r]  = n1i0;
                ar[1][r1] = n1r1; ai[1][r1] = n1i1;
            }
        }
    }
}

__global__ void __launch_bounds__(256, 3) qiskit_head_kernel(
    const float* __restrict__ x,       // (B, 512)
    const float* __restrict__ proj_w,  // (8, 512)
    const float* __restrict__ qnn_w,   // (72,)
    const float* __restrict__ out_w,   // (10, 8)
    const float* __restrict__ out_b,   // (10,)
    float* __restrict__ out,           // (B, 10)
    int B)
{
    __shared__ __align__(16) float s_pw[NQ * FDIM];   // 16 KB
    __shared__ float4 s_g4[DEPTH * NQ][2];
    __shared__ float  s_ow[NCLS * NQ];
    __shared__ float  s_ob[NCLS];

    const int tid  = threadIdx.x;
    const int lane = tid & 31;
    const int warp = tid >> 5;

    #pragma unroll 4
    for (int i = tid; i < NQ * FDIM; i += 256) s_pw[i] = proj_w[i];
    if (tid < NCLS * NQ) s_ow[tid] = out_w[tid];
    if (tid < NCLS)      s_ob[tid] = out_b[tid];
    if (tid < DEPTH * NQ) {
        float w0 = qnn_w[tid * 3 + 0];
        float w1 = qnn_w[tid * 3 + 1];
        float w2 = qnn_w[tid * 3 + 2];
        float c0, s0, c1, s1, c2, s2;
        sincosf(0.5f * w0, &s0, &c0);
        sincosf(0.5f * w1, &s1, &c1);
        sincosf(0.5f * w2, &s2, &c2);
        float2 A00 = { c1 * c0,  s1 * s0};
        float2 A01 = {-s1 * c0, -c1 * s0};
        float2 A10 = { s1 * c0, -c1 * s0};
        float2 A11 = { c1 * c0, -s1 * s0};
        float2 g00 = make_float2(c2 * A00.x + s2 * A10.y, c2 * A00.y - s2 * A10.x);
        float2 g01 = make_float2(c2 * A01.x + s2 * A11.y, c2 * A01.y - s2 * A11.x);
        float2 g10 = make_float2(c2 * A10.x + s2 * A00.y, c2 * A10.y - s2 * A00.x);
        float2 g11 = make_float2(c2 * A11.x + s2 * A01.y, c2 * A11.y - s2 * A01.x);
        s_g4[tid][0] = make_float4(g00.x, g00.y, g01.x, g01.y);
        s_g4[tid][1] = make_float4(g10.x, g10.y, g11.x, g11.y);
    }
    __syncthreads();

    auto mrg = [&](float a, float b, int dist) {
        float c = (lane & dist) ? b : a;
        float d = (lane & dist) ? a : b;
        return c + __shfl_xor_sync(FULL_MASK, d, dist);
    };
    auto srcLane = [](int q) { return ((q & 1) << 4) | (((q >> 1) & 1) << 3) | (((q >> 2) & 1) << 2); };

    const int b0 = (blockIdx.x * 8 + warp) * 2;   // two elements per warp
    const int b1 = b0 + 1;
    if (b0 >= B) return;
    const bool v1 = (b1 < B);

    // ---- projection: acc[e][q] = x[b_e] . proj_w[q] ----
    float acc[2][NQ];
    #pragma unroll
    for (int e = 0; e < 2; e++)
        #pragma unroll
        for (int q = 0; q < NQ; q++) acc[e][q] = 0.f;

    const float4* xr0 = (const float4*)(x + (size_t)b0 * FDIM);
    const float4* xr1 = (const float4*)(x + (size_t)(v1 ? b1 : b0) * FDIM);
    #pragma unroll
    for (int ch = 0; ch < 4; ch++) {
        float4 xv0 = xr0[ch * 32 + lane];
        float4 xv1 = xr1[ch * 32 + lane];
        #pragma unroll
        for (int q = 0; q < NQ; q++) {
            float4 wv = *(const float4*)&s_pw[q * FDIM + ch * 128 + lane * 4];
            acc[0][q] += xv0.x*wv.x + xv0.y*wv.y + xv0.z*wv.z + xv0.w*wv.w;
            acc[1][q] += xv1.x*wv.x + xv1.y*wv.y + xv1.z*wv.z + xv1.w*wv.w;
        }
    }
    // dual 9-shfl multi-reduce (interleaved)
    float fin[2];
    {
        float a0m0 = mrg(acc[0][0], acc[0][1], 16), a1m0 = mrg(acc[1][0], acc[1][1], 16);
        float a0m1 = mrg(acc[0][2], acc[0][3], 16), a1m1 = mrg(acc[1][2], acc[1][3], 16);
        float a0m2 = mrg(acc[0][4], acc[0][5], 16), a1m2 = mrg(acc[1][4], acc[1][5], 16);
        float a0m3 = mrg(acc[0][6], acc[0][7], 16), a1m3 = mrg(acc[1][6], acc[1][7], 16);
        float a0n0 = mrg(a0m0, a0m1, 8), a1n0 = mrg(a1m0, a1m1, 8);
        float a0n1 = mrg(a0m2, a0m3, 8), a1n1 = mrg(a1m2, a1m3, 8);
        float f0 = mrg(a0n0, a0n1, 4),   f1 = mrg(a1n0, a1n1, 4);
        f0 += __shfl_xor_sync(FULL_MASK, f0, 2); f1 += __shfl_xor_sync(FULL_MASK, f1, 2);
        f0 += __shfl_xor_sync(FULL_MASK, f0, 1); f1 += __shfl_xor_sync(FULL_MASK, f1, 1);
        fin[0] = f0; fin[1] = f1;
    }
    float cv[2], sv[2];
    #pragma unroll
    for (int e = 0; e < 2; e++) {
        float h = tanhf(fin[e]) * 0.78539816339744830962f;
        __sincosf(h, &sv[e], &cv[e]);
    }
    float cq[2][NQ], sq[2][NQ];
    #pragma unroll
    for (int q = 0; q < NQ; q++) {
        const int sl = srcLane(q);
        cq[0][q] = __shfl_sync(FULL_MASK, cv[0], sl);
        sq[0][q] = __shfl_sync(FULL_MASK, sv[0], sl);
        cq[1][q] = __shfl_sync(FULL_MASK, cv[1], sl);
        sq[1][q] = __shfl_sync(FULL_MASK, sv[1], sl);
    }

    // ---- state after encoding + layer-0 gates: product state ----
    float ar[2][8], ai[2][8];
    #pragma unroll
    for (int e = 0; e < 2; e++) {
        float Lr = 1.f, Li = 0.f;
        #pragma unroll
        for (int k = 0; k < 5; k++) {
            const int q = k + 3;
            float4 A = s_g4[q][0], Bv = s_g4[q][1];
            const bool bit = (lane >> k) & 1;
            float wx = bit ? (Bv.x*cq[e][q] + Bv.z*sq[e][q]) : (A.x*cq[e][q] + A.z*sq[e][q]);
            float wy = bit ? (Bv.y*cq[e][q] + Bv.w*sq[e][q]) : (A.y*cq[e][q] + A.w*sq[e][q]);
            float nr = Lr*wx - Li*wy;
            float ni = Lr*wy + Li*wx;
            Lr = nr; Li = ni;
        }
        float4 A0 = s_g4[0][0], B0 = s_g4[0][1];
        float a0x = A0.x*cq[e][0] + A0.z*sq[e][0], a0y = A0.y*cq[e][0] + A0.w*sq[e][0];
        float b0x = B0.x*cq[e][0] + B0.z*sq[e][0], b0y = B0.y*cq[e][0] + B0.w*sq[e][0];
        ar[e][0] = Lr*a0x - Li*a0y;  ai[e][0] = Lr*a0y + Li*a0x;
        ar[e][1] = Lr*b0x - Li*b0y;  ai[e][1] = Lr*b0y + Li*b0x;

        float4 A1 = s_g4[1][0], B1 = s_g4[1][1];
        float a1x = A1.x*cq[e][1] + A1.z*sq[e][1], a1y = A1.y*cq[e][1] + A1.w*sq[e][1];
        float b1x = B1.x*cq[e][1] + B1.z*sq[e][1], b1y = B1.y*cq[e][1] + B1.w*sq[e][1];
        #pragma unroll
        for (int r = 0; r < 2; r++) {
            float tr = ar[e][r], ti = ai[e][r];
            ar[e][r + 2] = tr*b1x - ti*b1y;  ai[e][r + 2] = tr*b1y + ti*b1x;
            ar[e][r]     = tr*a1x - ti*a1y;  ai[e][r]     = tr*a1y + ti*a1x;
        }

        float4 A2 = s_g4[2][0], B2 = s_g4[2][1];
        float a2x = A2.x*cq[e][2] + A2.z*sq[e][2], a2y = A2.y*cq[e][2] + A2.w*sq[e][2];
        float b2x = B2.x*cq[e][2] + B2.z*sq[e][2], b2y = B2.y*cq[e][2] + B2.w*sq[e][2];
        #pragma unroll
        for (int r = 0; r < 4; r++) {
            float tr = ar[e][r], ti = ai[e][r];
            ar[e][r + 4] = tr*b2x - ti*b2y;  ai[e][r + 4] = tr*b2y + ti*b2x;
            ar[e][r]     = tr*a2x - ti*a2y;  ai[e][r]     = tr*a2y + ti*a2x;
        }
    }

    // ---- layers 1,2 with deferred-CNOT masks (both elems interleaved) ----
    #define GATE(idx, PMv, Wv) gate_apply2<PMv, Wv>(ar, ai, s_g4[idx][0], s_g4[idx][1], lane)
    // layer 1 (phi = C)
    GATE(8,  0x03, 0xFE); GATE(9,  0x06, 0x03); GATE(10, 0x0C, 0x07); GATE(11, 0x18, 0x0F);
    GATE(12, 0x30, 0x1F); GATE(13, 0x60, 0x3F); GATE(14, 0xC0, 0x7F); GATE(15, 0x83, 0xFF);
    // layer 2 (phi = C^2)
    GATE(16, 0x05, 0xAB); GATE(17, 0x0A, 0xFD); GATE(18, 0x14, 0xFA); GATE(19, 0x28, 0xF5);
    GATE(20, 0x50, 0xEA); GATE(21, 0xA0, 0xD5); GATE(22, 0x43, 0xAA); GATE(23, 0x86, 0x55);
    #undef GATE

    // ---- PauliZ via Walsh-Hadamard of |amp|^2 (phi = C^3) ----
    float z[2][8];
    #pragma unroll
    for (int e = 0; e < 2; e++) {
        float S[8];
        #pragma unroll
        for (int r = 0; r < 8; r++) S[r] = ar[e][r]*ar[e][r] + ai[e][r]*ai[e][r];
        #pragma unroll
        for (int st = 0; st < 3; st++) {
            const int d = 1 << st;
            #pragma unroll
            for (int r = 0; r < 8; r++) {
                if (!(r & d)) {
                    float a = S[r] + S[r + d];
                    float bm = S[r] - S[r + d];
                    S[r] = a; S[r + d] = bm;
                }
            }
        }
        auto sg = [&](int wl, float v) { return (__popc(lane & wl) & 1) ? -v : v; };
        z[e][0] = sg(0x06, S[2]); z[e][1] = sg(0x0A, S[6]);
        z[e][2] = sg(0x15, S[4]); z[e][3] = sg(0x0B, S[1]);
        z[e][4] = sg(0x16, S[3]); z[e][5] = sg(0x0C, S[6]);
        z[e][6] = sg(0x19, S[4]); z[e][7] = sg(0x13, S[1]);
    }
    // dual 9-shfl multi-reduce (interleaved)
    float f0, f1;
    {
        float a0m0 = mrg(z[0][0], z[0][1], 16), a1m0 = mrg(z[1][0], z[1][1], 16);
        float a0m1 = mrg(z[0][2], z[0][3], 16), a1m1 = mrg(z[1][2], z[1][3], 16);
        float a0m2 = mrg(z[0][4], z[0][5], 16), a1m2 = mrg(z[1][4], z[1][5], 16);
        float a0m3 = mrg(z[0][6], z[0][7], 16), a1m3 = mrg(z[1][6], z[1][7], 16);
        float a0n0 = mrg(a0m0, a0m1, 8), a1n0 = mrg(a1m0, a1m1, 8);
        float a0n1 = mrg(a0m2, a0m3, 8), a1n1 = mrg(a1m2, a1m3, 8);
        f0 = mrg(a0n0, a0n1, 4);  f1 = mrg(a1n0, a1n1, 4);
        f0 += __shfl_xor_sync(FULL_MASK, f0, 2); f1 += __shfl_xor_sync(FULL_MASK, f1, 2);
        f0 += __shfl_xor_sync(FULL_MASK, f0, 1); f1 += __shfl_xor_sync(FULL_MASK, f1, 1);
    }
    float g0[NQ], g1[NQ];
    #pragma unroll
    for (int q = 0; q < NQ; q++) {
        const int sl = srcLane(q);
        g0[q] = __shfl_sync(FULL_MASK, f0, sl);
        g1[q] = __shfl_sync(FULL_MASK, f1, sl);
    }

    // ---- output head ----
    if (lane < NCLS) {
        float o0 = s_ob[lane], o1 = s_ob[lane];
        #pragma unroll
        for (int q = 0; q < NQ; q++) {
            float w = s_ow[lane * NQ + q];
            o0 += g0[q] * w;
            o1 += g1[q] * w;
        }
        out[(size_t)b0 * NCLS + lane] = o0;
        if (v1) out[(size_t)b1 * NCLS + lane] = o1;
    }
}

extern "C" void kernel_launch(void* const* d_in, const int* in_sizes, int n_in,
                              void* d_out, int out_size) {
    const float* x      = (const float*)d_in[0];
    const float* proj_w = (const float*)d_in[1];
    const float* qnn_w  = (const float*)d_in[2];
    const float* out_w  = (const float*)d_in[3];
    const float* out_b  = (const float*)d_in[4];
    float* out = (float*)d_out;

    int B = in_sizes[0] / FDIM;            // 8192
    int blocks = (B + 15) / 16;            // 512: two batch elems per warp
    qiskit_head_kernel<<<blocks, 256>>>(x, proj_w, qnn_w, out_w, out_b, out, B);
}